// round 8
// baseline (speedup 1.0000x reference)
#include <cuda_runtime.h>

#define BB 64
#define TT 4096
#define DD 128
#define HH 128
#define GG 384            // 3*H, gates [r, z, n]

#define NCTA  148
#define N_G1  16          // gemm1 CTAs, 4 batches each, all t
// roles after prologue: [0,64) rec0, [64,128) rec1, [128,144) gemm1, [144,148) exit

typedef unsigned long long u64;

// Scratch (device globals — no allocation allowed).
__device__ float g_gi0[(size_t)TT * BB * GG];
__device__ float g_gi1[(size_t)TT * BB * GG];
__device__ float g_h0 [(size_t)TT * BB * HH];
__device__ unsigned g_f_gi0[TT];     // gi0[t] ready (flag, target 1)
__device__ unsigned g_c_h0 [BB];     // per-batch monotone counter: #steps of h0 done
__device__ unsigned g_c_gi1[N_G1];   // per-gemm1-CTA monotone counter: #t of gi1 done

// ---- packed f32x2 + activation helpers -----------------------------------
__device__ __forceinline__ void fma2(u64& d, u64 a, u64 b) {
    asm("fma.rn.f32x2 %0, %1, %2, %0;" : "+l"(d) : "l"(a), "l"(b));
}
__device__ __forceinline__ u64 f2u(float x, float y) {
    u64 v; asm("mov.b64 %0, {%1,%2};" : "=l"(v) : "f"(x), "f"(y)); return v;
}
__device__ __forceinline__ float hsum(u64 a, u64 b) {
    float xl, xh, yl, yh;
    asm("mov.b64 {%0,%1}, %2;" : "=f"(xl), "=f"(xh) : "l"(a));
    asm("mov.b64 {%0,%1}, %2;" : "=f"(yl), "=f"(yh) : "l"(b));
    return (xl + xh) + (yl + yh);
}
__device__ __forceinline__ float fsig(float x) {
    return __fdividef(1.0f, 1.0f + __expf(-x));
}
__device__ __forceinline__ float ftanh(float x) {
    return 1.0f - __fdividef(2.0f, __expf(2.0f * x) + 1.0f);
}

// ---- flag primitives (gpu-scope release/acquire) -------------------------
__device__ __forceinline__ unsigned ld_acq(const unsigned* p) {
    unsigned v;
    asm volatile("ld.acquire.gpu.global.b32 %0, [%1];" : "=r"(v) : "l"(p));
    return v;
}
__device__ __forceinline__ void red_rel(unsigned* p) {
    asm volatile("red.release.gpu.global.add.u32 [%0], 1;" :: "l"(p) : "memory");
}
__device__ __forceinline__ void spin_ge(const unsigned* p, unsigned target) {
    while (ld_acq(p) < target) { __nanosleep(64); }
}

__global__ void zero_flags() {
    int i = blockIdx.x * blockDim.x + threadIdx.x;
    if (i < TT) g_f_gi0[i] = 0;
    if (i < BB) g_c_h0[i] = 0;
    if (i < N_G1) g_c_gi1[i] = 0;
}

// ---------------------------------------------------------------------------
struct SmemRec  { float h[128]; float gh[384]; };
struct SmemGemm { float x[2][4][128]; };       // double-buffered 4 activation rows
union  SmemAll  { SmemRec r; SmemGemm g; };

// ---------------------------------------------------------------------------
// Prologue: gi0[t] = x[:,t,:] @ W_ih0^T + b, t striped across all 148 CTAs.
// ---------------------------------------------------------------------------
__device__ void gi0_prologue(SmemGemm* sm,
                             const float* __restrict__ X,
                             const float* __restrict__ W,
                             const float* __restrict__ bias,
                             int t0)
{
    const int j = threadIdx.x;

    u64 w[64];
    {
        const ulonglong2* wr = (const ulonglong2*)(W + (size_t)j * 128);
        #pragma unroll
        for (int k = 0; k < 32; k++) { ulonglong2 v = wr[k]; w[2*k] = v.x; w[2*k+1] = v.y; }
    }
    const float bj = bias[j];

    for (int t = t0; t < TT; t += NCTA) {
        for (int m = 0; m < BB; m += 4) {
            for (int i = j; i < 4 * 128; i += 384) {
                const int r = i >> 7, c = i & 127;
                sm->x[0][r][c] = X[((size_t)(m + r) * TT + t) * DD + c];
            }
            __syncthreads();

            u64 a0 = f2u(bj, 0.f), b0 = 0;
            u64 a1 = f2u(bj, 0.f), b1 = 0;
            u64 a2 = f2u(bj, 0.f), b2 = 0;
            u64 a3 = f2u(bj, 0.f), b3 = 0;
            const ulonglong2* r0 = (const ulonglong2*)sm->x[0][0];
            const ulonglong2* r1 = (const ulonglong2*)sm->x[0][1];
            const ulonglong2* r2 = (const ulonglong2*)sm->x[0][2];
            const ulonglong2* r3 = (const ulonglong2*)sm->x[0][3];
            #pragma unroll
            for (int k = 0; k < 32; k++) {
                ulonglong2 v0 = r0[k], v1 = r1[k], v2 = r2[k], v3 = r3[k];
                fma2(a0, v0.x, w[2*k]); fma2(b0, v0.y, w[2*k+1]);
                fma2(a1, v1.x, w[2*k]); fma2(b1, v1.y, w[2*k+1]);
                fma2(a2, v2.x, w[2*k]); fma2(b2, v2.y, w[2*k+1]);
                fma2(a3, v3.x, w[2*k]); fma2(b3, v3.y, w[2*k+1]);
            }
            g_gi0[((size_t)t * BB + m + 0) * GG + j] = hsum(a0, b0);
            g_gi0[((size_t)t * BB + m + 1) * GG + j] = hsum(a1, b1);
            g_gi0[((size_t)t * BB + m + 2) * GG + j] = hsum(a2, b2);
            g_gi0[((size_t)t * BB + m + 3) * GG + j] = hsum(a3, b3);
            __syncthreads();
        }
        if (j == 0) red_rel(&g_f_gi0[t]);
    }
}

// ---------------------------------------------------------------------------
// gemm1: CTA g owns batches 4g..4g+3 for ALL t. gi1[t][b] = h0[t][b] @ W_ih1^T + b.
// Depends only on the 4 owning rec0 CTAs (per-batch counters). Double-buffered
// smem staging of h0 rows; t+1 loads issued before the FMA block of t.
// ---------------------------------------------------------------------------
__device__ void gemm1_role(SmemGemm* sm,
                           const float* __restrict__ W,
                           const float* __restrict__ bias,
                           int g)
{
    const int j = threadIdx.x;
    const int b0 = 4 * g;

    u64 w[64];
    {
        const ulonglong2* wr = (const ulonglong2*)(W + (size_t)j * 128);
        #pragma unroll
        for (int k = 0; k < 32; k++) { ulonglong2 v = wr[k]; w[2*k] = v.x; w[2*k+1] = v.y; }
    }
    const float bj = bias[j];

    if (j < 4) spin_ge(&g_c_h0[b0 + j], 1);
    __syncthreads();
    for (int i = j; i < 512; i += 384)
        sm->x[0][i >> 7][i & 127] = g_h0[((size_t)0 * BB + b0 + (i >> 7)) * HH + (i & 127)];
    __syncthreads();

    for (int t = 0; t < TT; t++) {
        const int cur = t & 1;
        if (t + 1 < TT && j < 4) spin_ge(&g_c_h0[b0 + j], (unsigned)(t + 2));
        __syncthreads();                  // spins resolved before staging loads

        float s0 = 0.f, s1 = 0.f;
        if (t + 1 < TT) {
            s0 = g_h0[((size_t)(t + 1) * BB + b0 + (j >> 7)) * HH + (j & 127)];
            if (j < 128)
                s1 = g_h0[((size_t)(t + 1) * BB + b0 + 3) * HH + j];
        }

        u64 a0 = f2u(bj, 0.f), c0 = 0;
        u64 a1 = f2u(bj, 0.f), c1 = 0;
        u64 a2 = f2u(bj, 0.f), c2 = 0;
        u64 a3 = f2u(bj, 0.f), c3 = 0;
        const ulonglong2* r0 = (const ulonglong2*)sm->x[cur][0];
        const ulonglong2* r1 = (const ulonglong2*)sm->x[cur][1];
        const ulonglong2* r2 = (const ulonglong2*)sm->x[cur][2];
        const ulonglong2* r3 = (const ulonglong2*)sm->x[cur][3];
        #pragma unroll
        for (int k = 0; k < 32; k++) {
            ulonglong2 v0 = r0[k], v1 = r1[k], v2 = r2[k], v3 = r3[k];
            fma2(a0, v0.x, w[2*k]); fma2(c0, v0.y, w[2*k+1]);
            fma2(a1, v1.x, w[2*k]); fma2(c1, v1.y, w[2*k+1]);
            fma2(a2, v2.x, w[2*k]); fma2(c2, v2.y, w[2*k+1]);
            fma2(a3, v3.x, w[2*k]); fma2(c3, v3.y, w[2*k+1]);
        }
        const size_t base = ((size_t)t * BB + b0) * GG + j;
        g_gi1[base + 0 * GG] = hsum(a0, c0);
        g_gi1[base + 1 * GG] = hsum(a1, c1);
        g_gi1[base + 2 * GG] = hsum(a2, c2);
        g_gi1[base + 3 * GG] = hsum(a3, c3);

        if (t + 1 < TT) {
            sm->x[1 - cur][j >> 7][j & 127] = s0;
            if (j < 128) sm->x[1 - cur][3][j] = s1;
        }
        __syncthreads();
        if (j == 0) red_rel(&g_c_gi1[g]);
    }
}

// ---------------------------------------------------------------------------
// REC role: 1 batch per CTA. dot -> bar A -> gates -> bar B, with gi for the
// NEXT step prefetched at loop bottom (flag pre-verified by thread 383).
// ---------------------------------------------------------------------------
__device__ void rec_role(SmemRec* sm,
                         const float* __restrict__ Whh,
                         const float* __restrict__ bhh,
                         int layer, int b,
                         float* __restrict__ hout)
{
    const int j = threadIdx.x;
    const int e = j & 127;
    const bool isGate = (j < 128);

    u64 w[64];
    {
        const ulonglong2* wr = (const ulonglong2*)(Whh + (size_t)j * 128);
        #pragma unroll
        for (int k = 0; k < 32; k++) { ulonglong2 v = wr[k]; w[2*k] = v.x; w[2*k+1] = v.y; }
    }
    const float bj = bhh[j];

    const float* gi = layer ? g_gi1 : g_gi0;
    const size_t S = (size_t)BB * GG;
    const float* gb = gi + (size_t)b * GG;
    const int cg = b >> 2;                 // gemm1 CTA owning this batch (layer 1)

    if (isGate) sm->h[e] = 0.0f;
    if (j == 0) {
        if (layer == 0) spin_ge(&g_f_gi0[0], 1);
        else            spin_ge(&g_c_gi1[cg], 1);
    }
    __syncthreads();

    float gr = 0.f, gz = 0.f, gn = 0.f;
    if (isGate) { gr = gb[e]; gz = gb[e + 128]; gn = gb[e + 256]; }
    float hreg = 0.0f;
    const ulonglong2* h16 = (const ulonglong2*)sm->h;

    for (int t = 0; t < TT; t++) {
        // dot: gh row j = b_hh[j] + h . W_hh[j]
        u64 a0 = f2u(bj, 0.f), a1 = 0;
        #pragma unroll
        for (int k = 0; k < 32; k++) {
            ulonglong2 v = h16[k];
            fma2(a0, v.x, w[2*k]);
            fma2(a1, v.y, w[2*k+1]);
        }
        sm->gh[j] = hsum(a0, a1);
        __syncthreads();                       // (A) gh ready

        // pre-verify next step's gi availability during the gate phase
        if (j == 383 && t + 1 < TT) {
            if (layer == 0) spin_ge(&g_f_gi0[t + 1], 1);
            else            spin_ge(&g_c_gi1[cg], (unsigned)(t + 2));
        }

        if (isGate) {
            const float r = fsig(sm->gh[e] + gr);
            const float z = fsig(sm->gh[e + 128] + gz);
            const float n = ftanh(gn + r * sm->gh[e + 256]);
            hreg = n + z * (hreg - n);
            sm->h[e] = hreg;
            if (layer == 0) g_h0[((size_t)t * BB + b) * HH + e] = hreg;
        }
        __syncthreads();                       // (B) h published; flag known
        if (layer == 0 && j == 0) red_rel(&g_c_h0[b]);

        // prefetch gi for t+1 (covered by next step's dot+gates)
        if (isGate && t + 1 < TT) {
            const float* p = gb + (size_t)(t + 1) * S;
            gr = p[e]; gz = p[e + 128]; gn = p[e + 256];
        }
    }

    if (isGate) hout[(size_t)b * HH + e] = hreg;
}

// ---------------------------------------------------------------------------
__global__ __launch_bounds__(384, 1) void gru_fused(
    const float* __restrict__ x,
    const float* __restrict__ W_ih0, const float* __restrict__ W_hh0,
    const float* __restrict__ b_ih0, const float* __restrict__ b_hh0,
    const float* __restrict__ W_ih1, const float* __restrict__ W_hh1,
    const float* __restrict__ b_ih1, const float* __restrict__ b_hh1,
    float* __restrict__ out)
{
    __shared__ __align__(16) SmemAll sm;
    const int bid = blockIdx.x;

    // Prologue: all CTAs compute gi0 striped over t.
    gi0_prologue(&sm.g, x, W_ih0, b_ih0, bid);
    __syncthreads();

    if (bid < 64) {
        rec_role(&sm.r, W_hh0, b_hh0, /*layer=*/0, bid, out);
    } else if (bid < 128) {
        rec_role(&sm.r, W_hh1, b_hh1, /*layer=*/1, bid - 64, out + BB * HH);
    } else if (bid < 128 + N_G1) {
        gemm1_role(&sm.g, W_ih1, b_ih1, bid - 128);
    }
    // bids 144-147: done after prologue
}

extern "C" void kernel_launch(void* const* d_in, const int* in_sizes, int n_in,
                              void* d_out, int out_size)
{
    const float* x     = (const float*)d_in[0];
    const float* W_ih0 = (const float*)d_in[1];
    const float* W_hh0 = (const float*)d_in[2];
    const float* b_ih0 = (const float*)d_in[3];
    const float* b_hh0 = (const float*)d_in[4];
    const float* W_ih1 = (const float*)d_in[5];
    const float* W_hh1 = (const float*)d_in[6];
    const float* b_ih1 = (const float*)d_in[7];
    const float* b_hh1 = (const float*)d_in[8];
    float* out = (float*)d_out;   // [L=2, B, H]

    zero_flags<<<(TT + 255) / 256, 256>>>();
    gru_fused<<<NCTA, 384>>>(
        x, W_ih0, W_hh0, b_ih0, b_hh0, W_ih1, W_hh1, b_ih1, b_hh1, out);
}

// round 9
// speedup vs baseline: 2.1394x; 2.1394x over previous
#include <cuda_runtime.h>

#define BB 64
#define TT 4096
#define DD 128
#define HH 128
#define GG 384            // 3*H, gates [r, z, n]

#define NC 16             // chunks
#define CC 256            // timesteps per chunk  (NC*CC == TT)

typedef unsigned long long u64;

// Scratch (device globals — no allocation allowed).
__device__ float g_gi0[(size_t)TT * BB * GG];
__device__ float g_gi1[(size_t)TT * BB * GG];
__device__ float g_h0 [(size_t)TT * BB * HH];   // layer-0 hidden trajectory
__device__ float g_hst1[BB * HH];               // layer-1 h state between chunks

// ---- packed f32x2 + activation helpers -----------------------------------
__device__ __forceinline__ void fma2(u64& d, u64 a, u64 b) {
    asm("fma.rn.f32x2 %0, %1, %2, %0;" : "+l"(d) : "l"(a), "l"(b));
}
__device__ __forceinline__ u64 f2u(float x, float y) {
    u64 v; asm("mov.b64 %0, {%1,%2};" : "=l"(v) : "f"(x), "f"(y)); return v;
}
__device__ __forceinline__ float hsum(u64 a, u64 b) {
    float xl, xh, yl, yh;
    asm("mov.b64 {%0,%1}, %2;" : "=f"(xl), "=f"(xh) : "l"(a));
    asm("mov.b64 {%0,%1}, %2;" : "=f"(yl), "=f"(yh) : "l"(b));
    return (xl + xh) + (yl + yh);
}
__device__ __forceinline__ float fsig(float x) {
    return __fdividef(1.0f, 1.0f + __expf(-x));
}
__device__ __forceinline__ float ftanh(float x) {
    return 1.0f - __fdividef(2.0f, __expf(2.0f * x) + 1.0f);
}

// ---------------------------------------------------------------------------
// gemm_chunk: gi[t] = act @ W^T + bias for the CC timesteps of chunk c.
// grid 128, 2 timesteps per CTA. which=0: act = x rows; which=1: act = h0 rows.
// ---------------------------------------------------------------------------
__global__ __launch_bounds__(384, 1) void gemm_chunk(
    const float* __restrict__ X,
    const float* __restrict__ W,
    const float* __restrict__ bias,
    int which, int c)
{
    const int j = threadIdx.x;

    u64 w[64];
    {
        const ulonglong2* wr = (const ulonglong2*)(W + (size_t)j * 128);
        #pragma unroll
        for (int k = 0; k < 32; k++) { ulonglong2 v = wr[k]; w[2*k] = v.x; w[2*k+1] = v.y; }
    }
    const float bj = bias[j];
    float* dst = which ? g_gi1 : g_gi0;

    __shared__ __align__(16) float sx[4][128];

    for (int t = c * CC + blockIdx.x; t < (c + 1) * CC; t += 128) {
        for (int m = 0; m < BB; m += 4) {
            for (int i = j; i < 4 * 128; i += 384) {
                const int r = i >> 7, cc = i & 127;
                const int b = m + r;
                sx[r][cc] = which
                    ? g_h0[((size_t)t * BB + b) * HH + cc]
                    : X[((size_t)b * TT + t) * DD + cc];
            }
            __syncthreads();

            u64 a0 = f2u(bj, 0.f), b0 = 0;
            u64 a1 = f2u(bj, 0.f), b1 = 0;
            u64 a2 = f2u(bj, 0.f), b2 = 0;
            u64 a3 = f2u(bj, 0.f), b3 = 0;
            const ulonglong2* r0 = (const ulonglong2*)sx[0];
            const ulonglong2* r1 = (const ulonglong2*)sx[1];
            const ulonglong2* r2 = (const ulonglong2*)sx[2];
            const ulonglong2* r3 = (const ulonglong2*)sx[3];
            #pragma unroll
            for (int k = 0; k < 32; k++) {
                ulonglong2 v0 = r0[k], v1 = r1[k], v2 = r2[k], v3 = r3[k];
                fma2(a0, v0.x, w[2*k]); fma2(b0, v0.y, w[2*k+1]);
                fma2(a1, v1.x, w[2*k]); fma2(b1, v1.y, w[2*k+1]);
                fma2(a2, v2.x, w[2*k]); fma2(b2, v2.y, w[2*k+1]);
                fma2(a3, v3.x, w[2*k]); fma2(b3, v3.y, w[2*k+1]);
            }
            dst[((size_t)t * BB + m + 0) * GG + j] = hsum(a0, b0);
            dst[((size_t)t * BB + m + 1) * GG + j] = hsum(a1, b1);
            dst[((size_t)t * BB + m + 2) * GG + j] = hsum(a2, b2);
            dst[((size_t)t * BB + m + 3) * GG + j] = hsum(a3, b3);
            __syncthreads();
        }
    }
}

// ---------------------------------------------------------------------------
// rec_chunk: GRU recurrence for CC timesteps, 1 batch per CTA (grid 64).
// Thread j owns W_hh row j in regs. Gate threads (j<128) own the r-rows and
// precompute r from their OWN accumulator before barrier A, so the
// post-barrier chain is just LDS + sigmoid(z) / tanh(n) + blend.
// h state persists across chunks: layer 0 via g_h0 trajectory; layer 1 via
// g_hst1. No flags — chunk ordering is done by stream events.
// ---------------------------------------------------------------------------
__global__ __launch_bounds__(384, 1) void rec_chunk(
    const float* __restrict__ Whh,
    const float* __restrict__ bhh,
    int layer, int c,
    float* __restrict__ hout)
{
    const int j = threadIdx.x;
    const int e = j & 127;
    const bool isGate = (j < 128);
    const int b = blockIdx.x;

    u64 w[64];
    {
        const ulonglong2* wr = (const ulonglong2*)(Whh + (size_t)j * 128);
        #pragma unroll
        for (int k = 0; k < 32; k++) { ulonglong2 v = wr[k]; w[2*k] = v.x; w[2*k+1] = v.y; }
    }
    const float bj = bhh[j];

    const float* gi = layer ? g_gi1 : g_gi0;
    const size_t S = (size_t)BB * GG;
    const float* pOwn = gi + (size_t)b * GG + j;         // rows 0-255: own gi stream
    const float* pN   = gi + (size_t)b * GG + 256 + e;   // gate threads: gi_n stream

    __shared__ __align__(16) float s_h[128];
    __shared__ float s_gh[256];    // [0:128) = gh_z+gi_z (pre-sigmoid), [128:256) = gh_n

    const int t0 = c * CC, t1 = t0 + CC;

    float hreg = 0.0f;
    if (isGate) {
        if (c == 0) hreg = 0.0f;
        else if (layer == 0) hreg = g_h0[((size_t)(t0 - 1) * BB + b) * HH + e];
        else hreg = g_hst1[b * HH + e];
        s_h[e] = hreg;
    }
    __syncthreads();

    float gOwn = (j < 256) ? pOwn[(size_t)t0 * S] : 0.0f;
    float gN   = isGate ? pN[(size_t)t0 * S] : 0.0f;

    const ulonglong2* h16 = (const ulonglong2*)s_h;

    for (int t = t0; t < t1; t++) {
        // dot: gh row j = b_hh[j] + h . W_hh[j]
        u64 a0 = f2u(bj, 0.f), a1 = 0;
        #pragma unroll
        for (int k = 0; k < 32; k++) {
            ulonglong2 v = h16[k];
            fma2(a0, v.x, w[2*k]);
            fma2(a1, v.y, w[2*k+1]);
        }
        const float acc = hsum(a0, a1);

        float r = 0.0f;
        if (j >= 128) {
            s_gh[j - 128] = acc + ((j < 256) ? gOwn : 0.0f);  // z fused; n raw
        } else {
            r = fsig(acc + gOwn);                              // r pre-barrier
        }
        __syncthreads();                       // (A) gh_z, gh_n ready

        if (isGate) {
            const float z = fsig(s_gh[e]);
            const float n = ftanh(gN + r * s_gh[e + 128]);
            hreg = n + z * (hreg - n);
            s_h[e] = hreg;
            if (layer == 0) g_h0[((size_t)t * BB + b) * HH + e] = hreg;
        }
        __syncthreads();                       // (B) h published

        if (t + 1 < t1) {                      // prefetch next step's gi
            const size_t off = (size_t)(t + 1) * S;
            if (j < 256) gOwn = pOwn[off];
            if (isGate)  gN   = pN[off];
        }
    }

    if (isGate) {
        if (layer == 1) g_hst1[b * HH + e] = hreg;
        if (c == NC - 1) hout[(size_t)b * HH + e] = hreg;
    }
}

// ---------------------------------------------------------------------------
// Launch: chunked 4-stage pipeline across 4 streams, ordered by events.
//   sA: gemm0(c)            -> evG0[c]
//   sB: wait evG0[c]; rec0(c) -> evR0[c]
//   sC: wait evR0[c]; gemm1(c) -> evG1[c]
//   0 : wait evG1[c]; rec1(c)          (origin stream; natural join)
// Streams/events created once, before any capture. Graph-capturable.
// ---------------------------------------------------------------------------
extern "C" void kernel_launch(void* const* d_in, const int* in_sizes, int n_in,
                              void* d_out, int out_size)
{
    const float* x     = (const float*)d_in[0];
    const float* W_ih0 = (const float*)d_in[1];
    const float* W_hh0 = (const float*)d_in[2];
    const float* b_ih0 = (const float*)d_in[3];
    const float* b_hh0 = (const float*)d_in[4];
    const float* W_ih1 = (const float*)d_in[5];
    const float* W_hh1 = (const float*)d_in[6];
    const float* b_ih1 = (const float*)d_in[7];
    const float* b_hh1 = (const float*)d_in[8];
    float* out = (float*)d_out;   // [L=2, B, H]

    static bool inited = false;
    static cudaStream_t sA, sB, sC;
    static cudaEvent_t evFork, evG0[NC], evR0[NC], evG1[NC];
    if (!inited) {
        cudaStreamCreateWithFlags(&sA, cudaStreamNonBlocking);
        cudaStreamCreateWithFlags(&sB, cudaStreamNonBlocking);
        cudaStreamCreateWithFlags(&sC, cudaStreamNonBlocking);
        cudaEventCreateWithFlags(&evFork, cudaEventDisableTiming);
        for (int i = 0; i < NC; i++) {
            cudaEventCreateWithFlags(&evG0[i], cudaEventDisableTiming);
            cudaEventCreateWithFlags(&evR0[i], cudaEventDisableTiming);
            cudaEventCreateWithFlags(&evG1[i], cudaEventDisableTiming);
        }
        inited = true;
    }

    // Fork side streams off the origin stream.
    cudaEventRecord(evFork, 0);
    cudaStreamWaitEvent(sA, evFork, 0);
    cudaStreamWaitEvent(sB, evFork, 0);
    cudaStreamWaitEvent(sC, evFork, 0);

    for (int c = 0; c < NC; c++) {
        gemm_chunk<<<128, 384, 0, sA>>>(x, W_ih0, b_ih0, /*which=*/0, c);
        cudaEventRecord(evG0[c], sA);
    }
    for (int c = 0; c < NC; c++) {
        cudaStreamWaitEvent(sB, evG0[c], 0);
        rec_chunk<<<64, 384, 0, sB>>>(W_hh0, b_hh0, /*layer=*/0, c, out);
        cudaEventRecord(evR0[c], sB);
    }
    for (int c = 0; c < NC; c++) {
        cudaStreamWaitEvent(sC, evR0[c], 0);
        gemm_chunk<<<128, 384, 0, sC>>>(nullptr, W_ih1, b_ih1, /*which=*/1, c);
        cudaEventRecord(evG1[c], sC);
    }
    for (int c = 0; c < NC; c++) {
        cudaStreamWaitEvent(0, evG1[c], 0);
        rec_chunk<<<64, 384, 0, 0>>>(W_hh1, b_hh1, /*layer=*/1, c, out + BB * HH);
    }
}